// round 10
// baseline (speedup 1.0000x reference)
#include <cuda_runtime.h>
#include <cuda_fp16.h>
#include <cuda_bf16.h>
#include <math.h>
#include <stdint.h>

#define BATCH   8
#define NN      64
#define KTOT    65536
#define SPLITS  64
#define KCH     (KTOT / SPLITS)   // 1024
#define TILE_K  128               // floats per row per tile (512B DRAM bursts)
#define NTILES  (KCH / TILE_K)    // 8
#define HSTRIDE 136               // fp16 smem row stride
#define ITERS   10

// Gram scratch [B][N][N]; zero at module load, re-zeroed by the tail.
__device__ float g_gram[BATCH * NN * NN];
// Per-batch CTA arrival counters; reset by the tail CTA each call.
__device__ unsigned int g_cnt[BATCH];

__device__ __forceinline__ uint32_t smem_u32(const void* p) {
    return (uint32_t)__cvta_generic_to_shared(p);
}

// ---------------------------------------------------------------------------
// Fused kernel: split-K Gram (fp16 mma m16n8k16 + ldmatrix) + CRF tail.
// grid = (SPLITS, BATCH) = 512 CTAs, block = 256 (8 warps: 4(M) x 2(N)).
// __launch_bounds__(256, 4): <=64 regs -> 4 CTAs/SM -> ONE wave of 512 CTAs
// (this is what R8 lacked; its 74 regs caused a 2-wave straggler regression).
// Last-arriving CTA per batch runs the CRF iterations + output.
// ---------------------------------------------------------------------------
__global__ void __launch_bounds__(256, 4) fused_kernel(const float* __restrict__ feats,
                                                       const float* __restrict__ logits,
                                                       const float* __restrict__ W,
                                                       float* __restrict__ out) {
    __shared__ __align__(16) __half hbuf[2][64 * HSTRIDE];   // 2 x 17 KB
    __shared__ float s_nrm[64];
    __shared__ float s_lg[64];
    __shared__ float s_e[2][64];
    __shared__ float s_red[64];
    __shared__ unsigned int s_ticket;

    const int tid  = threadIdx.x;
    const int wid  = tid >> 5;
    const int lane = tid & 31;
    const int tg   = lane & 3;
    const int wm   = wid >> 1;
    const int wn   = wid & 1;

    const int b = blockIdx.y;
    const int s = blockIdx.x;
    const float* base = feats + (size_t)b * NN * KTOT + (size_t)s * KCH;

    // fill mapping: warp w covers rows {w, w+8, ..., w+56}; a whole warp reads
    // 512B contiguous from one row per LDG.128 (DRAM page friendly).
    const int r0   = tid >> 5;
    const int coff = (tid & 31) * 4;

    const int a_row  = wm * 16 + (lane & 7) + ((lane >> 3) & 1) * 8;
    const int a_koff = (lane >> 4) * 8;
    const int b_col  = wn * 32 + (lane & 7) + ((lane >> 4) & 1) * 8;
    const int b_koff = ((lane >> 3) & 1) * 8;

    float c[4][4];
#pragma unroll
    for (int i = 0; i < 4; ++i)
#pragma unroll
        for (int j = 0; j < 4; ++j) c[i][j] = 0.0f;

#define FILL(buf, tptr)                                                              \
    do {                                                                             \
        _Pragma("unroll")                                                            \
        for (int i = 0; i < 8; ++i) {                                                \
            float4 v = *reinterpret_cast<const float4*>((tptr) + (size_t)(r0 + 8 * i) * KTOT + coff); \
            __half* H = &hbuf[buf][(r0 + 8 * i) * HSTRIDE + coff];                   \
            *reinterpret_cast<__half2*>(H)     = __float22half2_rn(make_float2(v.x, v.y)); \
            *reinterpret_cast<__half2*>(H + 2) = __float22half2_rn(make_float2(v.z, v.w)); \
        }                                                                            \
    } while (0)

    FILL(0, base);

    for (int t = 0; t < NTILES; ++t) {
        __syncthreads();   // buf[t&1] filled; everyone done reading buf[(t+1)&1]

        const __half* S = &hbuf[t & 1][0];
#pragma unroll
        for (int kk = 0; kk < 8; ++kk) {
            const int k0 = kk * 16;
            uint32_t a0, a1, a2, a3, b01[2], b23[2], b45[2], b67[2];
            {
                uint32_t addr = smem_u32(S + a_row * HSTRIDE + k0 + a_koff);
                asm volatile("ldmatrix.sync.aligned.m8n8.x4.shared.b16 {%0,%1,%2,%3}, [%4];"
                             : "=r"(a0), "=r"(a1), "=r"(a2), "=r"(a3) : "r"(addr));
            }
            {
                uint32_t addr = smem_u32(S + b_col * HSTRIDE + k0 + b_koff);
                asm volatile("ldmatrix.sync.aligned.m8n8.x4.shared.b16 {%0,%1,%2,%3}, [%4];"
                             : "=r"(b01[0]), "=r"(b01[1]), "=r"(b23[0]), "=r"(b23[1]) : "r"(addr));
            }
            {
                uint32_t addr = smem_u32(S + (b_col + 16) * HSTRIDE + k0 + b_koff);
                asm volatile("ldmatrix.sync.aligned.m8n8.x4.shared.b16 {%0,%1,%2,%3}, [%4];"
                             : "=r"(b45[0]), "=r"(b45[1]), "=r"(b67[0]), "=r"(b67[1]) : "r"(addr));
            }
#define MMA16(accv, bb)                                                         \
    asm volatile("mma.sync.aligned.m16n8k16.row.col.f32.f16.f16.f32 "          \
                 "{%0,%1,%2,%3}, {%4,%5,%6,%7}, {%8,%9}, {%0,%1,%2,%3};"       \
                 : "+f"(accv[0]), "+f"(accv[1]), "+f"(accv[2]), "+f"(accv[3])  \
                 : "r"(a0), "r"(a1), "r"(a2), "r"(a3), "r"(bb[0]), "r"(bb[1]))
            MMA16(c[0], b01);
            MMA16(c[1], b23);
            MMA16(c[2], b45);
            MMA16(c[3], b67);
#undef MMA16
        }

        if (t + 1 < NTILES) {
            const float* nxt = base + (t + 1) * TILE_K;
            FILL((t + 1) & 1, nxt);
        }
    }
#undef FILL

    // epilogue: atomic-accumulate partial C into g_gram[b]
    float* gb = g_gram + (size_t)b * NN * NN;
    const int re = wm * 16 + (lane >> 2);
#pragma unroll
    for (int nt = 0; nt < 4; ++nt) {
        const int col = wn * 32 + nt * 8 + tg * 2;
        atomicAdd(&gb[(re)     * NN + col    ], c[nt][0]);
        atomicAdd(&gb[(re)     * NN + col + 1], c[nt][1]);
        atomicAdd(&gb[(re + 8) * NN + col    ], c[nt][2]);
        atomicAdd(&gb[(re + 8) * NN + col + 1], c[nt][3]);
    }

    // ---- arrival protocol: last CTA of this batch runs the CRF tail ----
    __threadfence();                 // our partials visible before ticket bump
    __syncthreads();                 // all threads' atomics issued before ticket
    if (tid == 0) s_ticket = atomicAdd(&g_cnt[b], 1u);
    __syncthreads();
    if (s_ticket != SPLITS - 1) return;

    __threadfence();
    if (tid == 0) g_cnt[b] = 0;      // reset for next graph replay

    // ---- CRF tail (R7 scheme): thread (i = tid>>2, q = tid&3) ----
    const int i  = tid >> 2;
    const int q  = tid & 3;
    const int j0 = q * 16;

    if (tid < 64) {
        s_nrm[tid]  = sqrtf(gb[tid * NN + tid]);
        s_lg[tid]   = logits[b * NN + tid];
        s_e[0][tid] = 0.0f;
    }
    __syncthreads();

    const float ni = s_nrm[i];
    float pp[16];
#pragma unroll
    for (int jj = 0; jj < 16; ++jj) {
        const int j = j0 + jj;
        const float dot  = gb[i * NN + j];
        const float sim  = dot / (ni * s_nrm[j] + 1e-6f);
        const float wsym = 0.5f * (W[i * NN + j] + W[j * NN + i]);
        pp[jj] = sim * wsym;
    }
    // re-zero consumed gram slice for the next replay
#pragma unroll
    for (int jj = 0; jj < 16; jj += 4)
        *reinterpret_cast<float4*>(&gb[i * NN + j0 + jj]) = make_float4(0.f, 0.f, 0.f, 0.f);

    const float li = s_lg[i];
    int cur = 0;
    for (int it = 0; it < ITERS; ++it) {
        float acc = 0.0f;
        const float* e = s_e[cur];
#pragma unroll
        for (int jj = 0; jj < 16; ++jj) {
            const float x = li + e[j0 + jj];
            float t, r;
            asm("ex2.approx.f32 %0, %1;" : "=f"(t) : "f"(x * -1.4426950408889634f));
            asm("rcp.approx.f32 %0, %1;" : "=f"(r) : "f"(1.0f + t));
            acc = fmaf((1.0f - t) * r, pp[jj], acc);
        }
        acc += __shfl_xor_sync(0xFFFFFFFF, acc, 1);
        acc += __shfl_xor_sync(0xFFFFFFFF, acc, 2);
        if (q == 0) s_e[cur ^ 1][i] = acc;
        __syncthreads();
        cur ^= 1;
    }

    if (tid < 64) s_red[tid] = s_e[cur][tid];
    __syncthreads();
    if (tid < 32) {
        float v = s_red[tid] + s_red[tid + 32];
        v += __shfl_xor_sync(0xFFFFFFFF, v, 16);
        v += __shfl_xor_sync(0xFFFFFFFF, v, 8);
        v += __shfl_xor_sync(0xFFFFFFFF, v, 4);
        v += __shfl_xor_sync(0xFFFFFFFF, v, 2);
        v += __shfl_xor_sync(0xFFFFFFFF, v, 1);
        if (tid == 0) s_red[0] = v;
    }
    __syncthreads();
    if (tid < 64) {
        const float meanE = s_red[0] * (1.0f / 64.0f);
        out[b * NN + tid] = s_lg[tid] + meanE;
    }
}

extern "C" void kernel_launch(void* const* d_in, const int* in_sizes, int n_in,
                              void* d_out, int out_size) {
    const float* a_inter = (const float*)d_in[0];  // [8,64,64,32,32]
    const float* logits  = (const float*)d_in[1];  // [8,64]
    const float* W       = (const float*)d_in[2];  // [1,64,64]
    float* out           = (float*)d_out;          // [8,64]

    dim3 grid(SPLITS, BATCH);
    fused_kernel<<<grid, 256>>>(a_inter, logits, W, out);
}

// round 11
// speedup vs baseline: 1.0385x; 1.0385x over previous
#include <cuda_runtime.h>
#include <cuda_fp16.h>
#include <cuda_bf16.h>
#include <math.h>
#include <stdint.h>

#define BATCH   8
#define NN      64
#define KTOT    65536
#define SPLITS  64
#define KCH     (KTOT / SPLITS)   // 1024
#define TILE_K  64                // floats per tile row
#define NTILES  (KCH / TILE_K)    // 16
#define SSTRIDE 68                // fp32 staging row stride (floats)
#define HSTRIDE 72                // fp16 smem row stride (halves)
#define ITERS   10

// Gram scratch [B][N][N]; zero at module load, re-zeroed by crf_kernel.
__device__ float g_gram[BATCH * NN * NN];

__device__ __forceinline__ uint32_t smem_u32(const void* p) {
    return (uint32_t)__cvta_generic_to_shared(p);
}

// ---------------------------------------------------------------------------
// Kernel 1: split-K Gram, fp16 mma m16n8k16 + ldmatrix, cp.async staging.
// grid = (SPLITS, BATCH) = 512 CTAs, block = 256, occ 4 -> single wave.
// Pipeline per tile: wait stage -> convert fp32->fp16 -> sync ->
//                    issue cp.async for tile t+2 -> mma.
// Gmem latency covered by 2 tile-periods with zero register cost.
// ---------------------------------------------------------------------------
__global__ void __launch_bounds__(256, 4) gram_mma_kernel(const float* __restrict__ feats) {
    __shared__ __align__(16) float  fstage[2][64 * SSTRIDE];  // 2 x 17.4 KB
    __shared__ __align__(16) __half hbuf[2][64 * HSTRIDE];    // 2 x 9.2 KB

    const int tid  = threadIdx.x;
    const int wid  = tid >> 5;
    const int lane = tid & 31;
    const int tg   = lane & 3;
    const int wm   = wid >> 1;
    const int wn   = wid & 1;

    const int b = blockIdx.y;
    const int s = blockIdx.x;
    const float* base = feats + (size_t)b * NN * KTOT + (size_t)s * KCH;

    // data-movement mapping: 4 chunks (float4) per thread per tile
    // chunk ch = tid + 256k : row = ch>>4, c4 = ch&15  (16 chunks per 64-float row)
    int crow[4], cc4[4];
#pragma unroll
    for (int k = 0; k < 4; ++k) {
        const int ch = tid + 256 * k;
        crow[k] = ch >> 4;
        cc4[k]  = ch & 15;
    }

    const int a_row  = wm * 16 + (lane & 7) + ((lane >> 3) & 1) * 8;
    const int a_koff = (lane >> 4) * 8;
    const int b_col  = wn * 32 + (lane & 7) + ((lane >> 4) & 1) * 8;
    const int b_koff = ((lane >> 3) & 1) * 8;

    float c[4][4];
#pragma unroll
    for (int i = 0; i < 4; ++i)
#pragma unroll
        for (int j = 0; j < 4; ++j) c[i][j] = 0.0f;

#define CP_TILE(stg, t)                                                              \
    do {                                                                             \
        const float* g = base + (t) * TILE_K;                                        \
        _Pragma("unroll")                                                            \
        for (int k = 0; k < 4; ++k) {                                                \
            uint32_t dst = smem_u32(&fstage[stg][crow[k] * SSTRIDE + cc4[k] * 4]);   \
            const float* src = g + (size_t)crow[k] * KTOT + cc4[k] * 4;              \
            asm volatile("cp.async.cg.shared.global [%0], [%1], 16;"                 \
                         :: "r"(dst), "l"(src));                                     \
        }                                                                            \
        asm volatile("cp.async.commit_group;" ::: "memory");                         \
    } while (0)

    // prologue: stage tiles 0 and 1
    CP_TILE(0, 0);
    CP_TILE(1, 1);

    for (int t = 0; t < NTILES; ++t) {
        const int buf = t & 1;
        if (t + 1 < NTILES) {
            asm volatile("cp.async.wait_group 1;" ::: "memory");
        } else {
            asm volatile("cp.async.wait_group 0;" ::: "memory");
        }

        // convert fp32 stage -> fp16 buf (each thread its own 4 chunks)
#pragma unroll
        for (int k = 0; k < 4; ++k) {
            float4 v = *reinterpret_cast<const float4*>(&fstage[buf][crow[k] * SSTRIDE + cc4[k] * 4]);
            __half2 h0 = __float22half2_rn(make_float2(v.x, v.y));
            __half2 h1 = __float22half2_rn(make_float2(v.z, v.w));
            uint2 w = make_uint2(*(uint32_t*)&h0, *(uint32_t*)&h1);
            *reinterpret_cast<uint2*>(&hbuf[buf][crow[k] * HSTRIDE + cc4[k] * 4]) = w;
        }
        __syncthreads();   // converts done (stage[buf] free, hbuf[buf] ready)

        // refill the stage we just drained with tile t+2
        if (t + 2 < NTILES) CP_TILE(buf, t + 2);

        // mma over hbuf[buf]: 4 k-steps of 16
        const __half* S = &hbuf[buf][0];
#pragma unroll
        for (int kk = 0; kk < 4; ++kk) {
            const int k0 = kk * 16;
            uint32_t a0, a1, a2, a3, b01[2], b23[2], b45[2], b67[2];
            {
                uint32_t addr = smem_u32(S + a_row * HSTRIDE + k0 + a_koff);
                asm volatile("ldmatrix.sync.aligned.m8n8.x4.shared.b16 {%0,%1,%2,%3}, [%4];"
                             : "=r"(a0), "=r"(a1), "=r"(a2), "=r"(a3) : "r"(addr));
            }
            {
                uint32_t addr = smem_u32(S + b_col * HSTRIDE + k0 + b_koff);
                asm volatile("ldmatrix.sync.aligned.m8n8.x4.shared.b16 {%0,%1,%2,%3}, [%4];"
                             : "=r"(b01[0]), "=r"(b01[1]), "=r"(b23[0]), "=r"(b23[1]) : "r"(addr));
            }
            {
                uint32_t addr = smem_u32(S + (b_col + 16) * HSTRIDE + k0 + b_koff);
                asm volatile("ldmatrix.sync.aligned.m8n8.x4.shared.b16 {%0,%1,%2,%3}, [%4];"
                             : "=r"(b45[0]), "=r"(b45[1]), "=r"(b67[0]), "=r"(b67[1]) : "r"(addr));
            }
#define MMA16(accv, bb)                                                         \
    asm volatile("mma.sync.aligned.m16n8k16.row.col.f32.f16.f16.f32 "          \
                 "{%0,%1,%2,%3}, {%4,%5,%6,%7}, {%8,%9}, {%0,%1,%2,%3};"       \
                 : "+f"(accv[0]), "+f"(accv[1]), "+f"(accv[2]), "+f"(accv[3])  \
                 : "r"(a0), "r"(a1), "r"(a2), "r"(a3), "r"(bb[0]), "r"(bb[1]))
            MMA16(c[0], b01);
            MMA16(c[1], b23);
            MMA16(c[2], b45);
            MMA16(c[3], b67);
#undef MMA16
        }
    }
#undef CP_TILE

    // epilogue: atomic-accumulate partial C into g_gram[b]
    float* gb = g_gram + (size_t)b * NN * NN;
    const int re = wm * 16 + (lane >> 2);
#pragma unroll
    for (int nt = 0; nt < 4; ++nt) {
        const int col = wn * 32 + nt * 8 + tg * 2;
        atomicAdd(&gb[(re)     * NN + col    ], c[nt][0]);
        atomicAdd(&gb[(re)     * NN + col + 1], c[nt][1]);
        atomicAdd(&gb[(re + 8) * NN + col    ], c[nt][2]);
        atomicAdd(&gb[(re + 8) * NN + col + 1], c[nt][3]);
    }
}

// ---------------------------------------------------------------------------
// Kernel 2: CRF iterations + output (R7/R9 scheme). grid = BATCH, block = 256.
// Also re-zeroes g_gram for the next graph replay.
// ---------------------------------------------------------------------------
__global__ void __launch_bounds__(256) crf_kernel(const float* __restrict__ logits,
                                                  const float* __restrict__ W,
                                                  float* __restrict__ out) {
    const int b   = blockIdx.x;
    const int tid = threadIdx.x;
    const int i   = tid >> 2;
    const int q   = tid & 3;
    const int j0  = q * 16;

    __shared__ float nrm[64];
    __shared__ float lg[64];
    __shared__ float ebuf[2][64];
    __shared__ float red[64];

    float* gb = g_gram + (size_t)b * NN * NN;

    if (tid < 64) {
        nrm[tid] = sqrtf(gb[tid * NN + tid]);
        lg[tid]  = logits[b * NN + tid];
        ebuf[0][tid] = 0.0f;
    }
    __syncthreads();

    const float ni = nrm[i];
    float pp[16];
#pragma unroll
    for (int jj = 0; jj < 16; ++jj) {
        const int j = j0 + jj;
        const float dot  = gb[i * NN + j];
        const float sim  = dot / (ni * nrm[j] + 1e-6f);
        const float wsym = 0.5f * (W[i * NN + j] + W[j * NN + i]);
        pp[jj] = sim * wsym;
    }
#pragma unroll
    for (int jj = 0; jj < 16; jj += 4)
        *reinterpret_cast<float4*>(&gb[i * NN + j0 + jj]) = make_float4(0.f, 0.f, 0.f, 0.f);

    const float li = lg[i];
    int cur = 0;
    for (int it = 0; it < ITERS; ++it) {
        float acc = 0.0f;
        const float* e = ebuf[cur];
#pragma unroll
        for (int jj = 0; jj < 16; ++jj) {
            const float x = li + e[j0 + jj];
            float t, r;
            asm("ex2.approx.f32 %0, %1;" : "=f"(t) : "f"(x * -1.4426950408889634f));
            asm("rcp.approx.f32 %0, %1;" : "=f"(r) : "f"(1.0f + t));
            acc = fmaf((1.0f - t) * r, pp[jj], acc);
        }
        acc += __shfl_xor_sync(0xFFFFFFFF, acc, 1);
        acc += __shfl_xor_sync(0xFFFFFFFF, acc, 2);
        if (q == 0) ebuf[cur ^ 1][i] = acc;
        __syncthreads();
        cur ^= 1;
    }

    if (tid < 64) red[tid] = ebuf[cur][tid];
    __syncthreads();
    if (tid < 32) {
        float v = red[tid] + red[tid + 32];
        v += __shfl_xor_sync(0xFFFFFFFF, v, 16);
        v += __shfl_xor_sync(0xFFFFFFFF, v, 8);
        v += __shfl_xor_sync(0xFFFFFFFF, v, 4);
        v += __shfl_xor_sync(0xFFFFFFFF, v, 2);
        v += __shfl_xor_sync(0xFFFFFFFF, v, 1);
        if (tid == 0) red[0] = v;
    }
    __syncthreads();
    if (tid < 64) {
        const float meanE = red[0] * (1.0f / 64.0f);
        out[b * NN + tid] = lg[tid] + meanE;
    }
}

extern "C" void kernel_launch(void* const* d_in, const int* in_sizes, int n_in,
                              void* d_out, int out_size) {
    const float* a_inter = (const float*)d_in[0];  // [8,64,64,32,32]
    const float* logits  = (const float*)d_in[1];  // [8,64]
    const float* W       = (const float*)d_in[2];  // [1,64,64]
    float* out           = (float*)d_out;          // [8,64]

    dim3 grid(SPLITS, BATCH);
    gram_mma_kernel<<<grid, 256>>>(a_inter);

    crf_kernel<<<BATCH, 256>>>(logits, W, out);
}

// round 12
// speedup vs baseline: 1.1870x; 1.1430x over previous
#include <cuda_runtime.h>
#include <cuda_fp16.h>
#include <cuda_bf16.h>
#include <math.h>
#include <stdint.h>

#define BATCH   8
#define NN      64
#define KTOT    65536
#define SPLITS  32
#define KCH     (KTOT / SPLITS)   // 2048
#define TILE_K  128               // floats per tile row (512B bursts)
#define NTILES  (KCH / TILE_K)    // 16
#define HSTRIDE 136               // fp16 smem row stride (272B, conflict-free ldmatrix)
#define ITERS   10
#define NTHREADS 384              // 8 consumer warps + 4 producer warps

// Gram scratch [B][N][N]; zero at module load, re-zeroed by crf_kernel.
__device__ float g_gram[BATCH * NN * NN];

__device__ __forceinline__ uint32_t smem_u32(const void* p) {
    return (uint32_t)__cvta_generic_to_shared(p);
}

// named-barrier helpers (count = all 384 threads; arrivers don't block)
#define BAR_SYNC(id)   asm volatile("bar.sync %0, 384;"   :: "r"(id) : "memory")
#define BAR_ARRIVE(id) asm volatile("bar.arrive %0, 384;" :: "r"(id) : "memory")
// ids: 1+buf = full[buf] (producers arrive, consumers sync)
//      3+buf = empty[buf] (consumers arrive, producers sync)

// ---------------------------------------------------------------------------
// Kernel 1: warp-specialized split-K Gram.
// grid = (SPLITS, BATCH) = 256 CTAs, block = 384, occ 2 -> single wave.
// Producer warps 8-11 stream tiles gmem->fp16 smem (512B row bursts);
// consumer warps 0-7 run the proven ldmatrix + m16n8k16 mma pipeline.
// ---------------------------------------------------------------------------
__global__ void __launch_bounds__(NTHREADS, 2) gram_mma_kernel(const float* __restrict__ feats) {
    __shared__ __align__(16) __half hbuf[2][64 * HSTRIDE];   // 2 x 17 KB

    const int tid  = threadIdx.x;
    const int wid  = tid >> 5;
    const int lane = tid & 31;

    const int b = blockIdx.y;
    const int s = blockIdx.x;
    const float* base = feats + (size_t)b * NN * KTOT + (size_t)s * KCH;

    if (wid >= 8) {
        // ---------------- producer warps (4): rows [16*pw, 16*pw+16) ----------
        const int pw = wid - 8;
        const int rbase = pw * 16;
        for (int t = 0; t < NTILES; ++t) {
            const int buf = t & 1;
            if (t >= 2) BAR_SYNC(3 + buf);          // wait consumers done with buf
            const float* g = base + t * TILE_K;
            // 16 rows; whole warp covers one row (32 lanes x 16B = 512B burst).
            // Two batches of 8 to bound register liveness (~32 regs).
#pragma unroll
            for (int h = 0; h < 2; ++h) {
                float4 v[8];
#pragma unroll
                for (int i = 0; i < 8; ++i) {
                    const int row = rbase + h * 8 + i;
                    v[i] = *reinterpret_cast<const float4*>(g + (size_t)row * KTOT + lane * 4);
                }
#pragma unroll
                for (int i = 0; i < 8; ++i) {
                    const int row = rbase + h * 8 + i;
                    __half2 h0 = __float22half2_rn(make_float2(v[i].x, v[i].y));
                    __half2 h1 = __float22half2_rn(make_float2(v[i].z, v[i].w));
                    uint2 w = make_uint2(*(uint32_t*)&h0, *(uint32_t*)&h1);
                    *reinterpret_cast<uint2*>(&hbuf[buf][row * HSTRIDE + lane * 4]) = w;
                }
            }
            BAR_ARRIVE(1 + buf);                    // buf full
        }
        return;                                     // producers exit
    }

    // ---------------- consumer warps (8): 4(M) x 2(N) mma layout --------------
    const int tg = lane & 3;
    const int wm = wid >> 1;
    const int wn = wid & 1;

    const int a_row  = wm * 16 + (lane & 7) + ((lane >> 3) & 1) * 8;
    const int a_koff = (lane >> 4) * 8;
    const int b_col  = wn * 32 + (lane & 7) + ((lane >> 4) & 1) * 8;
    const int b_koff = ((lane >> 3) & 1) * 8;

    float c[4][4];
#pragma unroll
    for (int i = 0; i < 4; ++i)
#pragma unroll
        for (int j = 0; j < 4; ++j) c[i][j] = 0.0f;

    for (int t = 0; t < NTILES; ++t) {
        const int buf = t & 1;
        BAR_SYNC(1 + buf);                          // wait buf full

        const __half* S = &hbuf[buf][0];
#pragma unroll
        for (int kk = 0; kk < 8; ++kk) {
            const int k0 = kk * 16;
            uint32_t a0, a1, a2, a3, b01[2], b23[2], b45[2], b67[2];
            {
                uint32_t addr = smem_u32(S + a_row * HSTRIDE + k0 + a_koff);
                asm volatile("ldmatrix.sync.aligned.m8n8.x4.shared.b16 {%0,%1,%2,%3}, [%4];"
                             : "=r"(a0), "=r"(a1), "=r"(a2), "=r"(a3) : "r"(addr));
            }
            {
                uint32_t addr = smem_u32(S + b_col * HSTRIDE + k0 + b_koff);
                asm volatile("ldmatrix.sync.aligned.m8n8.x4.shared.b16 {%0,%1,%2,%3}, [%4];"
                             : "=r"(b01[0]), "=r"(b01[1]), "=r"(b23[0]), "=r"(b23[1]) : "r"(addr));
            }
            {
                uint32_t addr = smem_u32(S + (b_col + 16) * HSTRIDE + k0 + b_koff);
                asm volatile("ldmatrix.sync.aligned.m8n8.x4.shared.b16 {%0,%1,%2,%3}, [%4];"
                             : "=r"(b45[0]), "=r"(b45[1]), "=r"(b67[0]), "=r"(b67[1]) : "r"(addr));
            }
#define MMA16(accv, bb)                                                         \
    asm volatile("mma.sync.aligned.m16n8k16.row.col.f32.f16.f16.f32 "          \
                 "{%0,%1,%2,%3}, {%4,%5,%6,%7}, {%8,%9}, {%0,%1,%2,%3};"       \
                 : "+f"(accv[0]), "+f"(accv[1]), "+f"(accv[2]), "+f"(accv[3])  \
                 : "r"(a0), "r"(a1), "r"(a2), "r"(a3), "r"(bb[0]), "r"(bb[1]))
            MMA16(c[0], b01);
            MMA16(c[1], b23);
            MMA16(c[2], b45);
            MMA16(c[3], b67);
#undef MMA16
        }
        BAR_ARRIVE(3 + buf);                        // buf empty
    }

    // epilogue: atomic-accumulate partial C into g_gram[b]
    float* gb = g_gram + (size_t)b * NN * NN;
    const int re = wm * 16 + (lane >> 2);
#pragma unroll
    for (int nt = 0; nt < 4; ++nt) {
        const int col = wn * 32 + nt * 8 + tg * 2;
        atomicAdd(&gb[(re)     * NN + col    ], c[nt][0]);
        atomicAdd(&gb[(re)     * NN + col + 1], c[nt][1]);
        atomicAdd(&gb[(re + 8) * NN + col    ], c[nt][2]);
        atomicAdd(&gb[(re + 8) * NN + col + 1], c[nt][3]);
    }
}

// ---------------------------------------------------------------------------
// Kernel 2: CRF iterations + output (R7/R9 scheme). grid = BATCH, block = 256.
// Also re-zeroes g_gram for the next graph replay.
// ---------------------------------------------------------------------------
__global__ void __launch_bounds__(256) crf_kernel(const float* __restrict__ logits,
                                                  const float* __restrict__ W,
                                                  float* __restrict__ out) {
    const int b   = blockIdx.x;
    const int tid = threadIdx.x;
    const int i   = tid >> 2;
    const int q   = tid & 3;
    const int j0  = q * 16;

    __shared__ float nrm[64];
    __shared__ float lg[64];
    __shared__ float ebuf[2][64];
    __shared__ float red[64];

    float* gb = g_gram + (size_t)b * NN * NN;

    if (tid < 64) {
        nrm[tid] = sqrtf(gb[tid * NN + tid]);
        lg[tid]  = logits[b * NN + tid];
        ebuf[0][tid] = 0.0f;
    }
    __syncthreads();

    const float ni = nrm[i];
    float pp[16];
#pragma unroll
    for (int jj = 0; jj < 16; ++jj) {
        const int j = j0 + jj;
        const float dot  = gb[i * NN + j];
        const float sim  = dot / (ni * nrm[j] + 1e-6f);
        const float wsym = 0.5f * (W[i * NN + j] + W[j * NN + i]);
        pp[jj] = sim * wsym;
    }
#pragma unroll
    for (int jj = 0; jj < 16; jj += 4)
        *reinterpret_cast<float4*>(&gb[i * NN + j0 + jj]) = make_float4(0.f, 0.f, 0.f, 0.f);

    const float li = lg[i];
    int cur = 0;
    for (int it = 0; it < ITERS; ++it) {
        float acc = 0.0f;
        const float* e = ebuf[cur];
#pragma unroll
        for (int jj = 0; jj < 16; ++jj) {
            const float x = li + e[j0 + jj];
            float t, r;
            asm("ex2.approx.f32 %0, %1;" : "=f"(t) : "f"(x * -1.4426950408889634f));
            asm("rcp.approx.f32 %0, %1;" : "=f"(r) : "f"(1.0f + t));
            acc = fmaf((1.0f - t) * r, pp[jj], acc);
        }
        acc += __shfl_xor_sync(0xFFFFFFFF, acc, 1);
        acc += __shfl_xor_sync(0xFFFFFFFF, acc, 2);
        if (q == 0) ebuf[cur ^ 1][i] = acc;
        __syncthreads();
        cur ^= 1;
    }

    if (tid < 64) red[tid] = ebuf[cur][tid];
    __syncthreads();
    if (tid < 32) {
        float v = red[tid] + red[tid + 32];
        v += __shfl_xor_sync(0xFFFFFFFF, v, 16);
        v += __shfl_xor_sync(0xFFFFFFFF, v, 8);
        v += __shfl_xor_sync(0xFFFFFFFF, v, 4);
        v += __shfl_xor_sync(0xFFFFFFFF, v, 2);
        v += __shfl_xor_sync(0xFFFFFFFF, v, 1);
        if (tid == 0) red[0] = v;
    }
    __syncthreads();
    if (tid < 64) {
        const float meanE = red[0] * (1.0f / 64.0f);
        out[b * NN + tid] = lg[tid] + meanE;
    }
}

extern "C" void kernel_launch(void* const* d_in, const int* in_sizes, int n_in,
                              void* d_out, int out_size) {
    const float* a_inter = (const float*)d_in[0];  // [8,64,64,32,32]
    const float* logits  = (const float*)d_in[1];  // [8,64]
    const float* W       = (const float*)d_in[2];  // [1,64,64]
    float* out           = (float*)d_out;          // [8,64]

    dim3 grid(SPLITS, BATCH);
    gram_mma_kernel<<<grid, NTHREADS>>>(a_inter);

    crf_kernel<<<BATCH, 256>>>(logits, W, out);
}